// round 6
// baseline (speedup 1.0000x reference)
#include <cuda_runtime.h>

// KVCacheHeadAttention: B=32, E=4096 -> D=128, MAX_TOKENS=2048.
// Prefix-softmax: out[b,s,:] = sum_{t<=s} e_t*v[b,t,:] / sum_{t<=s} e_t.
// R5: ONE kernel. First 96 CTAs compute QKV split-K partials (release-
// counter publish); all CTAs acquire-spin, reduce partials, then do
// score+chunk-total+decoupled-lookback+scan. Scoped release/acquire
// (no __threadfence -> no CCTL.IVALL L1 flush). State self-resets for
// graph replay (last block zeroes flags/counters).

#define BB 32
#define DD 128
#define D4 32
#define EE 4096
#define MAXT 2048
#define CHUNK 128
#define MAXCH 16
#define NSPLIT 8
#define NPROD 96            // 3 matrices * 4 dtiles * 8 esplits
#define ECH 128

__device__ float g_part[3][NSPLIT][BB][DD];  // qkv GEMM partials
__device__ float g_ctot[BB][MAXCH][DD];      // chunk numerator totals
__device__ float g_dtot[BB][MAXCH];          // chunk denominator totals
__device__ int   g_flag[BB][MAXCH];          // chunk publish flags
__device__ int   g_qcnt;                     // qkv producers done
__device__ int   g_done;                     // blocks finished

__device__ __forceinline__ float4 f4add(float4 a, float4 b) {
    return make_float4(a.x+b.x, a.y+b.y, a.z+b.z, a.w+b.w);
}
__device__ __forceinline__ float4 f4fma(float s, float4 v, float4 a) {
    return make_float4(fmaf(s,v.x,a.x), fmaf(s,v.y,a.y),
                       fmaf(s,v.z,a.z), fmaf(s,v.w,a.w));
}
__device__ __forceinline__ float4 f4scale(float4 v, float s) {
    return make_float4(v.x*s, v.y*s, v.z*s, v.w*s);
}
__device__ __forceinline__ void st_release_gpu(int* p, int v) {
    asm volatile("st.release.gpu.global.b32 [%0], %1;" :: "l"(p), "r"(v) : "memory");
}
__device__ __forceinline__ int ld_acquire_gpu(const int* p) {
    int v;
    asm volatile("ld.acquire.gpu.global.b32 %0, [%1];" : "=r"(v) : "l"(p) : "memory");
    return v;
}
__device__ __forceinline__ void red_add_release_gpu(int* p, int v) {
    asm volatile("red.release.gpu.global.add.s32 [%0], %1;" :: "l"(p), "r"(v) : "memory");
}

__global__ __launch_bounds__(512, 3) void fused_all(
    const float* __restrict__ x,  const float* __restrict__ Wq,
    const float* __restrict__ Wk, const float* __restrict__ Wv,
    const float* __restrict__ kv, const int* __restrict__ np,
    float* __restrict__ out, int max_k) {

    __shared__ union {
        struct { float xs[32][ECH + 4]; float ws[32][ECH + 4]; } g;
        struct {
            float  qs[DD], kn[DD], es[CHUNK], rden[CHUNK];
            float4 vns4[D4];
            float4 part[16][D4];
            float  pden[16];
            float  warp_sums[4];
            int    last;
        } s;
    } u;

    int tid = threadIdx.x;
    int b   = blockIdx.y, c = blockIdx.x;
    int lin = blockIdx.y * gridDim.x + blockIdx.x;
    int nblocks = gridDim.x * gridDim.y;

    // ================= Phase A: QKV partial GEMM (first NPROD blocks) ====
    if (lin < NPROD) {
        int m   = lin >> 5;          // 0..2 matrix
        int r   = lin & 31;
        int dt  = r >> 3;            // 0..3 d-tile
        int esp = r & 7;             // 0..7 e-split (512 each)
        const float* W = (m == 0) ? Wq : ((m == 1) ? Wk : Wv);

        int ti = tid & 31;           // batch row
        int tj = tid >> 5;           // 0..15 -> d pair {tj, tj+16}
        float a0 = 0.f, a1 = 0.f;

        for (int ch = 0; ch < 4; ch++) {
            int e0 = esp * 512 + ch * ECH;
            for (int i = tid; i < 32 * (ECH / 4); i += 512) {
                int rr = i >> 5;
                int j  = (i & 31) << 2;
                *(float4*)&u.g.xs[rr][j] = *(const float4*)(x + (size_t)rr * EE + e0 + j);
                *(float4*)&u.g.ws[rr][j] = *(const float4*)(W + (size_t)(dt * 32 + rr) * EE + e0 + j);
            }
            __syncthreads();
            #pragma unroll
            for (int e = 0; e < ECH; e += 4) {
                float4 xa = *(float4*)&u.g.xs[ti][e];
                float4 wa = *(float4*)&u.g.ws[tj][e];
                float4 wb = *(float4*)&u.g.ws[tj + 16][e];
                a0 += xa.x*wa.x + xa.y*wa.y + xa.z*wa.z + xa.w*wa.w;
                a1 += xa.x*wb.x + xa.y*wb.y + xa.z*wb.z + xa.w*wb.w;
            }
            __syncthreads();
        }
        g_part[m][esp][ti][dt * 32 + tj]      = a0;
        g_part[m][esp][ti][dt * 32 + tj + 16] = a1;
        __syncthreads();                 // all partial stores done
        if (tid == 0) red_add_release_gpu(&g_qcnt, 1);
    }

    // ================= Phase B: wait for QKV, reduce partials ============
    if (tid == 0) {
        while (ld_acquire_gpu(&g_qcnt) < NPROD) { __nanosleep(128); }
    }
    __syncthreads();

    if (tid < 3 * DD) {
        int m = tid >> 7, d = tid & 127;
        float acc = 0.f;
        #pragma unroll
        for (int e = 0; e < NSPLIT; e++) acc += g_part[m][e][b][d];
        if (m == 0)      u.s.qs[d] = acc;
        else if (m == 1) u.s.kn[d] = acc;
        else             ((float*)u.s.vns4)[d] = acc;
    }
    __syncthreads();

    int npos = np[b];
    int t0   = c * CHUNK;

    // ================= Phase C: scores (4 lanes per token) ===============
    {
        int tok = tid >> 2, qq = tid & 3;
        int t   = t0 + tok;
        const float* krow = (t == npos) ? u.s.kn
                          : kv + ((size_t)b * MAXT + t) * DD;
        float sdot = 0.0f;
        int d0 = qq * 32;
        #pragma unroll
        for (int d = 0; d < 32; d += 4) {
            float4 kk = *(const float4*)(krow + d0 + d);
            sdot += u.s.qs[d0+d]*kk.x + u.s.qs[d0+d+1]*kk.y
                  + u.s.qs[d0+d+2]*kk.z + u.s.qs[d0+d+3]*kk.w;
        }
        sdot += __shfl_xor_sync(0xffffffffu, sdot, 1);
        sdot += __shfl_xor_sync(0xffffffffu, sdot, 2);
        float e = (t < max_k) ? expf(sdot * 0.08838834764831845f) : 0.0f;
        if (qq == 0) u.s.es[tok] = e;
    }
    __syncthreads();

    // ========== Phase D: 8-token numerator partials + den warp-scan ======
    int s  = tid >> 5;       // 0..15 warp = 8-token sub-chunk
    int d4 = tid & 31;
    int tb = t0 + s * 8;
    const float4* vbase = (const float4*)(kv + (size_t)BB * MAXT * DD
                                          + ((size_t)b * MAXT + tb) * DD) + d4;
    {
        float4 psum = make_float4(0.f, 0.f, 0.f, 0.f);
        #pragma unroll
        for (int uu = 0; uu < 8; uu++) {
            float4 xv = vbase[(size_t)uu * D4];
            if (tb + uu == npos) xv = u.s.vns4[d4];
            psum = f4fma(u.s.es[s * 8 + uu], xv, psum);
        }
        u.s.part[s][d4] = psum;
    }
    float dv = 0.0f;
    if (tid < 128) {
        dv = u.s.es[tid];
        int lane = tid & 31;
        #pragma unroll
        for (int o = 1; o < 32; o <<= 1) {
            float n = __shfl_up_sync(0xffffffffu, dv, o);
            if (lane >= o) dv += n;
        }
        if (lane == 31) u.s.warp_sums[tid >> 5] = dv;
    }
    __syncthreads();

    // exclusive prefix over own sub-chunk partials; publish chunk totals
    float4 pref = make_float4(0.f, 0.f, 0.f, 0.f);
    for (int j = 0; j < s; j++) pref = f4add(pref, u.s.part[j][d4]);
    if (s == 15)
        *((float4*)&g_ctot[b][c][0] + d4) = f4add(pref, u.s.part[15][d4]);
    if (tid == 0)
        g_dtot[b][c] = u.s.warp_sums[0] + u.s.warp_sums[1]
                     + u.s.warp_sums[2] + u.s.warp_sums[3];
    __syncthreads();
    if (tid == 0) st_release_gpu(&g_flag[b][c], 1);

    // ============= Phase E: lookback (warp i fetches predecessor i) ======
    if (s < c) {
        if (d4 == 0) {
            while (ld_acquire_gpu(&g_flag[b][s]) == 0) { __nanosleep(64); }
        }
        __syncwarp();
        u.s.part[s][d4] = *((const float4*)&g_ctot[b][s][0] + d4);
        if (d4 == 0) u.s.pden[s] = g_dtot[b][s];
    } else {
        u.s.part[s][d4] = make_float4(0.f, 0.f, 0.f, 0.f);
        if (d4 == 0) u.s.pden[s] = 0.0f;
    }
    __syncthreads();

    // bases + reciprocal denominators
    float4 bnum = make_float4(0.f, 0.f, 0.f, 0.f);
    float  bden = 0.0f;
    for (int i = 0; i < c; i++) {
        bnum = f4add(bnum, u.s.part[i][d4]);
        bden += u.s.pden[i];
    }
    if (tid < 128) {
        int w = tid >> 5;
        float wb = bden;
        for (int i = 0; i < w; i++) wb += u.s.warp_sums[i];
        u.s.rden[tid] = 1.0f / (wb + dv);
    }
    __syncthreads();

    // ================= Phase F: final scan + output ======================
    float4 acc = f4add(bnum, pref);
    float4* obase = (float4*)(out + ((size_t)b * max_k + tb) * DD) + d4;
    #pragma unroll
    for (int uu = 0; uu < 8; uu++) {
        float4 xv = vbase[(size_t)uu * D4];
        if (tb + uu == npos) xv = u.s.vns4[d4];
        acc = f4fma(u.s.es[s * 8 + uu], xv, acc);
        if (tb + uu < max_k)
            obase[(size_t)uu * D4] = f4scale(acc, u.s.rden[s * 8 + uu]);
    }

    // ================= Phase G: self-clean for graph replay ==============
    if (tid == 0) u.s.last = (atomicAdd(&g_done, 1) == nblocks - 1);
    __syncthreads();
    if (u.s.last) {
        if (tid < BB * MAXCH) ((int*)g_flag)[tid] = 0;
        if (tid == 0) { g_qcnt = 0; g_done = 0; }
    }
}

// ----------------------------------------------------------------- launch
extern "C" void kernel_launch(void* const* d_in, const int* in_sizes, int n_in,
                              void* d_out, int out_size) {
    const float* x   = (const float*)d_in[0];
    const float* Wq  = (const float*)d_in[1];
    const float* Wk  = (const float*)d_in[2];
    const float* Wv  = (const float*)d_in[3];
    const float* kvc = (const float*)d_in[4];
    const int*   np  = (const int*)d_in[5];
    float* out = (float*)d_out;

    int max_k   = out_size / (BB * DD);
    int nchunks = (max_k + CHUNK - 1) / CHUNK;   // 12 for max_k=1536

    fused_all<<<dim3(nchunks, BB), 512>>>(x, Wq, Wk, Wv, kvc, np, out, max_k);
}